// round 16
// baseline (speedup 1.0000x reference)
#include <cuda_runtime.h>
#include <cuda_fp16.h>
#include <cstdint>

#define NN 50000
#define CC 128
#define EE 640000
#define KK 40
#define LN_EPS 1e-5f
#define SCAN_BS 1024
#define MAX_NB 64

// Scratch
__device__ int    g_cnt[NN];
__device__ int    g_rowstart[NN + 1];
__device__ int    g_cursor[NN];
__device__ int    g_tmp[NN];
__device__ int    g_bsum[MAX_NB];
__device__ float  g_dinv[NN];
__device__ __half g_hs[(size_t)NN * CC];  // dinv-prescaled h, fp16
__device__ int    g_esrc[EE];             // CSR: src only

__device__ __forceinline__ uint32_t f2tf32(float f) {
    uint32_t r;
    asm("cvt.rna.tf32.f32 %0, %1;" : "=r"(r) : "f"(f));
    return r;
}

// ---------------------------------------------------------------- degree ----
__global__ void k_count(const int* __restrict__ dst, int e) {
    int i = blockIdx.x * blockDim.x + threadIdx.x;
    if (i < e) atomicAdd(&g_cnt[dst[i]], 1);
}

// 4 edges per thread: 4 independent atomic chains (MLP=4)
__global__ void k_count4(const int* __restrict__ dst, int e4) {
    int i = blockIdx.x * blockDim.x + threadIdx.x;
    if (i >= e4) return;
    int4 d = ((const int4*)dst)[i];
    atomicAdd(&g_cnt[d.x], 1);
    atomicAdd(&g_cnt[d.y], 1);
    atomicAdd(&g_cnt[d.z], 1);
    atomicAdd(&g_cnt[d.w], 1);
}

// ------------------------------------------------------------------ scan ----
// warp-shuffle scan: 2 barriers instead of 20
__global__ void k_scan1(int n) {
    __shared__ int wsum[32];
    int tid = threadIdx.x;
    int lane = tid & 31, wid = tid >> 5;
    int i = blockIdx.x * SCAN_BS + tid;
    int sv = (i < n) ? g_cnt[i] : 0;
#pragma unroll
    for (int off = 1; off < 32; off <<= 1) {
        int t = __shfl_up_sync(0xffffffffu, sv, off);
        if (lane >= off) sv += t;
    }
    if (lane == 31) wsum[wid] = sv;
    __syncthreads();
    if (wid == 0) {
        int w = wsum[lane];
#pragma unroll
        for (int off = 1; off < 32; off <<= 1) {
            int t = __shfl_up_sync(0xffffffffu, w, off);
            if (lane >= off) w += t;
        }
        wsum[lane] = w;
    }
    __syncthreads();
    if (wid > 0) sv += wsum[wid - 1];
    if (i < n) g_tmp[i] = sv;
    if (tid == SCAN_BS - 1) g_bsum[blockIdx.x] = sv;
}

__global__ void k_scan23(int n, int e, int nb) {
    __shared__ int sb[MAX_NB];
    int t = threadIdx.x;
    int b = blockIdx.x;
    if (t < MAX_NB) sb[t] = (t < nb) ? g_bsum[t] : 0;
    __syncthreads();
    if (t == 0) {
        int acc = 0;
        for (int i = 0; i < nb; i++) { int v = sb[i]; sb[i] = acc; acc += v; }
    }
    __syncthreads();
    int boff = sb[b];
    int i = b * SCAN_BS + t;
    if (i < n) {
        int c = g_cnt[i];
        int excl = g_tmp[i] - c + boff;
        g_rowstart[i] = excl;
        g_cursor[i] = excl;
        g_dinv[i] = rsqrtf((float)c + 1.0f);
        if (i == 0) g_rowstart[n] = e;
    }
}

// ------------------------------------------------------------ CSR fill ------
__global__ void k_fill(const int* __restrict__ src, const int* __restrict__ dst, int e) {
    int i = blockIdx.x * blockDim.x + threadIdx.x;
    if (i >= e) return;
    int d = dst[i];
    int pos = atomicAdd(&g_cursor[d], 1);
    g_esrc[pos] = src[i];
}

// 4 edges per thread: 4 independent atomic+store chains (MLP=4)
__global__ void k_fill4(const int* __restrict__ src, const int* __restrict__ dst, int e4) {
    int i = blockIdx.x * blockDim.x + threadIdx.x;
    if (i >= e4) return;
    int4 s = ((const int4*)src)[i];
    int4 d = ((const int4*)dst)[i];
    int p0 = atomicAdd(&g_cursor[d.x], 1);
    int p1 = atomicAdd(&g_cursor[d.y], 1);
    int p2 = atomicAdd(&g_cursor[d.z], 1);
    int p3 = atomicAdd(&g_cursor[d.w], 1);
    g_esrc[p0] = s.x;
    g_esrc[p1] = s.y;
    g_esrc[p2] = s.z;
    g_esrc[p3] = s.w;
}

// ----------- hs = fp16( dinv * (x @ W_conv) ) via mma.sync tf32 -------------
#define ASTR 132
#define BSTR 136
#define GEMM_SMEM ((128 * ASTR + 128 * BSTR) * 4)

__global__ void __launch_bounds__(256, 1)
k_gemm_mma(const float* __restrict__ x, const float* __restrict__ W, int n) {
    extern __shared__ float sm[];
    float* As = sm;                 // [128][ASTR]
    float* Bs = sm + 128 * ASTR;    // [128][BSTR]
    int t = threadIdx.x;
    int w = t >> 5, lane = t & 31;
    int m0 = blockIdx.x * 128;

    for (int i = t; i < 128 * 32; i += 256) {
        int r = i >> 5, cs = i & 31;
        float4 v = make_float4(0.f, 0.f, 0.f, 0.f);
        if (m0 + r < n) v = ((const float4*)(x + (size_t)(m0 + r) * CC))[cs];
        float4 tv;
        tv.x = __uint_as_float(f2tf32(v.x));
        tv.y = __uint_as_float(f2tf32(v.y));
        tv.z = __uint_as_float(f2tf32(v.z));
        tv.w = __uint_as_float(f2tf32(v.w));
        *(float4*)(As + r * ASTR + cs * 4) = tv;
    }
    for (int i = t; i < 128 * 32; i += 256) {
        int r = i >> 5, cs = i & 31;
        float4 v = ((const float4*)(W + (size_t)r * CC))[cs];
        float4 tv;
        tv.x = __uint_as_float(f2tf32(v.x));
        tv.y = __uint_as_float(f2tf32(v.y));
        tv.z = __uint_as_float(f2tf32(v.z));
        tv.w = __uint_as_float(f2tf32(v.w));
        *(float4*)(Bs + r * BSTR + cs * 4) = tv;
    }
    __syncthreads();

    int wm = (w & 3) * 32;
    int wn = (w >> 2) * 64;
    int grp = lane >> 2;
    int qd  = lane & 3;

    float c[2][8][4];
#pragma unroll
    for (int mi = 0; mi < 2; mi++)
#pragma unroll
        for (int ni = 0; ni < 8; ni++)
#pragma unroll
            for (int q = 0; q < 4; q++) c[mi][ni][q] = 0.f;

#pragma unroll
    for (int k0 = 0; k0 < 128; k0 += 8) {
        uint32_t a[2][4];
#pragma unroll
        for (int mi = 0; mi < 2; mi++) {
            int r0 = wm + mi * 16 + grp;
            a[mi][0] = __float_as_uint(As[r0 * ASTR + k0 + qd]);
            a[mi][1] = __float_as_uint(As[(r0 + 8) * ASTR + k0 + qd]);
            a[mi][2] = __float_as_uint(As[r0 * ASTR + k0 + qd + 4]);
            a[mi][3] = __float_as_uint(As[(r0 + 8) * ASTR + k0 + qd + 4]);
        }
        uint32_t b[8][2];
#pragma unroll
        for (int ni = 0; ni < 8; ni++) {
            int nc = wn + ni * 8 + grp;
            b[ni][0] = __float_as_uint(Bs[(k0 + qd) * BSTR + nc]);
            b[ni][1] = __float_as_uint(Bs[(k0 + qd + 4) * BSTR + nc]);
        }
#pragma unroll
        for (int mi = 0; mi < 2; mi++)
#pragma unroll
            for (int ni = 0; ni < 8; ni++) {
                asm volatile(
                    "mma.sync.aligned.m16n8k8.row.col.f32.tf32.tf32.f32 "
                    "{%0,%1,%2,%3}, {%4,%5,%6,%7}, {%8,%9}, {%0,%1,%2,%3};"
                    : "+f"(c[mi][ni][0]), "+f"(c[mi][ni][1]),
                      "+f"(c[mi][ni][2]), "+f"(c[mi][ni][3])
                    : "r"(a[mi][0]), "r"(a[mi][1]), "r"(a[mi][2]), "r"(a[mi][3]),
                      "r"(b[ni][0]), "r"(b[ni][1]));
            }
    }

    // epilogue: scale row by dinv[row], convert to fp16 -> hs
#pragma unroll
    for (int mi = 0; mi < 2; mi++) {
        int r0 = m0 + wm + mi * 16 + grp;
        float d0 = (r0 < n) ? g_dinv[r0] : 0.f;
        float d1 = (r0 + 8 < n) ? g_dinv[r0 + 8] : 0.f;
#pragma unroll
        for (int ni = 0; ni < 8; ni++) {
            int col = wn + ni * 8 + 2 * qd;
            if (r0 < n)
                *(__half2*)(g_hs + (size_t)r0 * CC + col) =
                    __floats2half2_rn(c[mi][ni][0] * d0, c[mi][ni][1] * d0);
            if (r0 + 8 < n)
                *(__half2*)(g_hs + (size_t)(r0 + 8) * CC + col) =
                    __floats2half2_rn(c[mi][ni][2] * d1, c[mi][ni][3] * d1);
        }
    }
}

// ------------- fused: CSR aggregate + relu*x + LN + residual + fc ----------
// 256 threads = 8 warps, one warp per node (8 warps/CTA = L1tex queue knee).
__global__ void k_aggfin(const float* __restrict__ x,
                         const float* __restrict__ bconv,
                         const float* __restrict__ gamma,
                         const float* __restrict__ beta,
                         const float* __restrict__ Wfc,
                         const float* __restrict__ bfc,
                         float* __restrict__ out, int n) {
    __shared__ float Wfs[CC * KK];
    __shared__ float bcs[CC], gs[CC], bs[CC], bfs[KK];
    __shared__ float ybuf[8][CC];

    int t = threadIdx.x;
    for (int i = t; i < CC * KK; i += 256) Wfs[i] = Wfc[i];
    if (t < CC) { bcs[t] = bconv[t]; gs[t] = gamma[t]; bs[t] = beta[t]; }
    if (t < KK) bfs[t] = bfc[t];
    __syncthreads();

    int wid = t >> 5;
    int lane = t & 31;
    int node = blockIdx.x * 8 + wid;
    if (node >= n) return;

    int rs = g_rowstart[node];
    int re = g_rowstart[node + 1];
    float dn = g_dinv[node];

    // seed with self row (fp16 -> fp32)
    float4 acc;
    {
        uint2 raw = *((const uint2*)(g_hs + (size_t)node * CC) + lane);
        float2 f0 = __half22float2(*(__half2*)&raw.x);
        float2 f1 = __half22float2(*(__half2*)&raw.y);
        acc = make_float4(f0.x, f0.y, f1.x, f1.y);
    }

    for (int base = rs; base < re; base += 32) {
        int idx = base + lane;
        int s = (idx < re) ? g_esrc[idx] : 0;
        int m = min(32, re - base);
        int j = 0;
        for (; j + 8 <= m; j += 8) {
            int ss[8]; uint2 vv[8];
#pragma unroll
            for (int q = 0; q < 8; q++)
                ss[q] = __shfl_sync(0xffffffffu, s, j + q);
#pragma unroll
            for (int q = 0; q < 8; q++)
                vv[q] = *((const uint2*)(g_hs + (size_t)ss[q] * CC) + lane);
#pragma unroll
            for (int q = 0; q < 8; q++) {
                float2 f0 = __half22float2(*(__half2*)&vv[q].x);
                float2 f1 = __half22float2(*(__half2*)&vv[q].y);
                acc.x += f0.x; acc.y += f0.y; acc.z += f1.x; acc.w += f1.y;
            }
        }
        for (; j + 4 <= m; j += 4) {
            int ss[4]; uint2 vv[4];
#pragma unroll
            for (int q = 0; q < 4; q++)
                ss[q] = __shfl_sync(0xffffffffu, s, j + q);
#pragma unroll
            for (int q = 0; q < 4; q++)
                vv[q] = *((const uint2*)(g_hs + (size_t)ss[q] * CC) + lane);
#pragma unroll
            for (int q = 0; q < 4; q++) {
                float2 f0 = __half22float2(*(__half2*)&vv[q].x);
                float2 f1 = __half22float2(*(__half2*)&vv[q].y);
                acc.x += f0.x; acc.y += f0.y; acc.z += f1.x; acc.w += f1.y;
            }
        }
        for (; j < m; j++) {
            int sj = __shfl_sync(0xffffffffu, s, j);
            uint2 raw = *((const uint2*)(g_hs + (size_t)sj * CC) + lane);
            float2 f0 = __half22float2(*(__half2*)&raw.x);
            float2 f1 = __half22float2(*(__half2*)&raw.y);
            acc.x += f0.x; acc.y += f0.y; acc.z += f1.x; acc.w += f1.y;
        }
    }

    // apply dinv[node], then bias, relu, *x, LN, +x, fc
    float4 xv = ((const float4*)(x + (size_t)node * CC))[lane];
    float4 bc = ((const float4*)bcs)[lane];
    acc.x = fmaxf(fmaf(acc.x, dn, bc.x), 0.f) * xv.x;
    acc.y = fmaxf(fmaf(acc.y, dn, bc.y), 0.f) * xv.y;
    acc.z = fmaxf(fmaf(acc.z, dn, bc.z), 0.f) * xv.z;
    acc.w = fmaxf(fmaf(acc.w, dn, bc.w), 0.f) * xv.w;

    float sU = acc.x + acc.y + acc.z + acc.w;
    float qU = acc.x * acc.x + acc.y * acc.y + acc.z * acc.z + acc.w * acc.w;
#pragma unroll
    for (int off = 16; off >= 1; off >>= 1) {
        sU += __shfl_xor_sync(0xffffffffu, sU, off);
        qU += __shfl_xor_sync(0xffffffffu, qU, off);
    }
    float mu = sU * (1.0f / CC);
    float var = qU * (1.0f / CC) - mu * mu;
    float rstd = rsqrtf(var + LN_EPS);

    float4 g = ((const float4*)gs)[lane];
    float4 b = ((const float4*)bs)[lane];
    float4 y;
    y.x = (acc.x - mu) * rstd * g.x + b.x + xv.x;
    y.y = (acc.y - mu) * rstd * g.y + b.y + xv.y;
    y.z = (acc.z - mu) * rstd * g.z + b.z + xv.z;
    y.w = (acc.w - mu) * rstd * g.w + b.w + xv.w;
    ((float4*)ybuf[wid])[lane] = y;
    __syncwarp();

    for (int k = lane; k < KK; k += 32) {
        float a2 = bfs[k];
#pragma unroll 8
        for (int c = 0; c < CC; c++)
            a2 = fmaf(ybuf[wid][c], Wfs[c * KK + k], a2);
        out[(size_t)node * KK + k] = a2;
    }
}

// ---------------------------------------------------------------- launch ----
extern "C" void kernel_launch(void* const* d_in, const int* in_sizes, int n_in,
                              void* d_out, int out_size) {
    const float* x  = (const float*)d_in[0];
    const int*   ei = (const int*)d_in[1];
    const float* Wc = (const float*)d_in[2];
    const float* bc = (const float*)d_in[3];
    const float* gm = (const float*)d_in[4];
    const float* bt = (const float*)d_in[5];
    const float* Wf = (const float*)d_in[6];
    const float* bf = (const float*)d_in[7];
    float* out = (float*)d_out;

    int n = in_sizes[0] / CC;
    int e = in_sizes[1] / 2;
    const int* src = ei;
    const int* dst = ei + e;
    int nb = (n + SCAN_BS - 1) / SCAN_BS;

    static void* cnt_ptr = nullptr;
    if (cnt_ptr == nullptr) {
        cudaGetSymbolAddress(&cnt_ptr, g_cnt);
        cudaFuncSetAttribute(k_gemm_mma, cudaFuncAttributeMaxDynamicSharedMemorySize,
                             GEMM_SMEM);
    }

    bool vec4 = ((e & 3) == 0) &&
                ((((uintptr_t)src) & 15) == 0) &&
                ((((uintptr_t)dst) & 15) == 0);

    cudaMemsetAsync(cnt_ptr, 0, (size_t)n * sizeof(int), 0);
    if (vec4) {
        int e4 = e >> 2;
        k_count4<<<(e4 + 255) / 256, 256>>>(dst, e4);
    } else {
        k_count<<<(e + 255) / 256, 256>>>(dst, e);
    }
    k_scan1<<<nb, SCAN_BS>>>(n);
    k_scan23<<<nb, SCAN_BS>>>(n, e, nb);
    if (vec4) {
        int e4 = e >> 2;
        k_fill4<<<(e4 + 255) / 256, 256>>>(src, dst, e4);
    } else {
        k_fill<<<(e + 255) / 256, 256>>>(src, dst, e);
    }

    k_gemm_mma<<<(n + 127) / 128, 256, GEMM_SMEM>>>(x, Wc, n);

    k_aggfin<<<(n + 7) / 8, 256>>>(x, bc, gm, bt, Wf, bf, out, n);
}

// round 17
// speedup vs baseline: 1.3786x; 1.3786x over previous
#include <cuda_runtime.h>
#include <cuda_fp16.h>
#include <cstdint>

#define NN 50000
#define CC 128
#define EE 640000
#define KK 40
#define LN_EPS 1e-5f
#define SCAN_BS 1024
#define MAX_NB 64

// Scratch
__device__ int    g_cnt[NN];
__device__ int    g_rowstart[NN + 1];
__device__ int    g_cursor[NN];
__device__ int    g_tmp[NN];
__device__ int    g_bsum[MAX_NB];
__device__ float  g_dinv[NN];
__device__ __half g_hs[(size_t)NN * CC];  // dinv-prescaled h, fp16
__device__ int    g_esrc[EE];             // CSR: src only
__device__ float  g_y[(size_t)NN * CC];   // LN output (pre-FC)

__device__ __forceinline__ uint32_t f2tf32(float f) {
    uint32_t r;
    asm("cvt.rna.tf32.f32 %0, %1;" : "=r"(r) : "f"(f));
    return r;
}

// ---------------------------------------------------------------- degree ----
__global__ void k_count(const int* __restrict__ dst, int e) {
    int i = blockIdx.x * blockDim.x + threadIdx.x;
    if (i < e) atomicAdd(&g_cnt[dst[i]], 1);
}

// ------------------------------------------------------------------ scan ----
__global__ void k_scan1(int n) {
    __shared__ int sm[SCAN_BS];
    int i = blockIdx.x * SCAN_BS + threadIdx.x;
    int v = (i < n) ? g_cnt[i] : 0;
    sm[threadIdx.x] = v;
    __syncthreads();
#pragma unroll
    for (int off = 1; off < SCAN_BS; off <<= 1) {
        int t = (threadIdx.x >= off) ? sm[threadIdx.x - off] : 0;
        __syncthreads();
        sm[threadIdx.x] += t;
        __syncthreads();
    }
    if (i < n) g_tmp[i] = sm[threadIdx.x];
    if (threadIdx.x == SCAN_BS - 1) g_bsum[blockIdx.x] = sm[SCAN_BS - 1];
}

__global__ void k_scan23(int n, int e, int nb) {
    __shared__ int sb[MAX_NB];
    int t = threadIdx.x;
    int b = blockIdx.x;
    if (t < MAX_NB) sb[t] = (t < nb) ? g_bsum[t] : 0;
    __syncthreads();
    if (t == 0) {
        int acc = 0;
        for (int i = 0; i < nb; i++) { int v = sb[i]; sb[i] = acc; acc += v; }
    }
    __syncthreads();
    int boff = sb[b];
    int i = b * SCAN_BS + t;
    if (i < n) {
        int c = g_cnt[i];
        int excl = g_tmp[i] - c + boff;
        g_rowstart[i] = excl;
        g_cursor[i] = excl;
        g_dinv[i] = rsqrtf((float)c + 1.0f);
        if (i == 0) g_rowstart[n] = e;
    }
}

// ------------------------------------------------------------ CSR fill ------
__global__ void k_fill(const int* __restrict__ src, const int* __restrict__ dst, int e) {
    int i = blockIdx.x * blockDim.x + threadIdx.x;
    if (i >= e) return;
    int d = dst[i];
    int pos = atomicAdd(&g_cursor[d], 1);
    g_esrc[pos] = src[i];
}

// ----------- hs = fp16( dinv * (x @ W_conv) ) via mma.sync tf32 -------------
#define ASTR 132
#define BSTR 136
#define GEMM_SMEM ((128 * ASTR + 128 * BSTR) * 4)

__global__ void __launch_bounds__(256, 1)
k_gemm_mma(const float* __restrict__ x, const float* __restrict__ W, int n) {
    extern __shared__ float sm[];
    float* As = sm;                 // [128][ASTR]
    float* Bs = sm + 128 * ASTR;    // [128][BSTR]
    int t = threadIdx.x;
    int w = t >> 5, lane = t & 31;
    int m0 = blockIdx.x * 128;

    for (int i = t; i < 128 * 32; i += 256) {
        int r = i >> 5, cs = i & 31;
        float4 v = make_float4(0.f, 0.f, 0.f, 0.f);
        if (m0 + r < n) v = ((const float4*)(x + (size_t)(m0 + r) * CC))[cs];
        float4 tv;
        tv.x = __uint_as_float(f2tf32(v.x));
        tv.y = __uint_as_float(f2tf32(v.y));
        tv.z = __uint_as_float(f2tf32(v.z));
        tv.w = __uint_as_float(f2tf32(v.w));
        *(float4*)(As + r * ASTR + cs * 4) = tv;
    }
    for (int i = t; i < 128 * 32; i += 256) {
        int r = i >> 5, cs = i & 31;
        float4 v = ((const float4*)(W + (size_t)r * CC))[cs];
        float4 tv;
        tv.x = __uint_as_float(f2tf32(v.x));
        tv.y = __uint_as_float(f2tf32(v.y));
        tv.z = __uint_as_float(f2tf32(v.z));
        tv.w = __uint_as_float(f2tf32(v.w));
        *(float4*)(Bs + r * BSTR + cs * 4) = tv;
    }
    __syncthreads();

    int wm = (w & 3) * 32;
    int wn = (w >> 2) * 64;
    int grp = lane >> 2;
    int qd  = lane & 3;

    float c[2][8][4];
#pragma unroll
    for (int mi = 0; mi < 2; mi++)
#pragma unroll
        for (int ni = 0; ni < 8; ni++)
#pragma unroll
            for (int q = 0; q < 4; q++) c[mi][ni][q] = 0.f;

#pragma unroll
    for (int k0 = 0; k0 < 128; k0 += 8) {
        uint32_t a[2][4];
#pragma unroll
        for (int mi = 0; mi < 2; mi++) {
            int r0 = wm + mi * 16 + grp;
            a[mi][0] = __float_as_uint(As[r0 * ASTR + k0 + qd]);
            a[mi][1] = __float_as_uint(As[(r0 + 8) * ASTR + k0 + qd]);
            a[mi][2] = __float_as_uint(As[r0 * ASTR + k0 + qd + 4]);
            a[mi][3] = __float_as_uint(As[(r0 + 8) * ASTR + k0 + qd + 4]);
        }
        uint32_t b[8][2];
#pragma unroll
        for (int ni = 0; ni < 8; ni++) {
            int nc = wn + ni * 8 + grp;
            b[ni][0] = __float_as_uint(Bs[(k0 + qd) * BSTR + nc]);
            b[ni][1] = __float_as_uint(Bs[(k0 + qd + 4) * BSTR + nc]);
        }
#pragma unroll
        for (int mi = 0; mi < 2; mi++)
#pragma unroll
            for (int ni = 0; ni < 8; ni++) {
                asm volatile(
                    "mma.sync.aligned.m16n8k8.row.col.f32.tf32.tf32.f32 "
                    "{%0,%1,%2,%3}, {%4,%5,%6,%7}, {%8,%9}, {%0,%1,%2,%3};"
                    : "+f"(c[mi][ni][0]), "+f"(c[mi][ni][1]),
                      "+f"(c[mi][ni][2]), "+f"(c[mi][ni][3])
                    : "r"(a[mi][0]), "r"(a[mi][1]), "r"(a[mi][2]), "r"(a[mi][3]),
                      "r"(b[ni][0]), "r"(b[ni][1]));
            }
    }

    // epilogue: scale row by dinv[row], convert to fp16 -> hs
#pragma unroll
    for (int mi = 0; mi < 2; mi++) {
        int r0 = m0 + wm + mi * 16 + grp;
        float d0 = (r0 < n) ? g_dinv[r0] : 0.f;
        float d1 = (r0 + 8 < n) ? g_dinv[r0 + 8] : 0.f;
#pragma unroll
        for (int ni = 0; ni < 8; ni++) {
            int col = wn + ni * 8 + 2 * qd;
            if (r0 < n)
                *(__half2*)(g_hs + (size_t)r0 * CC + col) =
                    __floats2half2_rn(c[mi][ni][0] * d0, c[mi][ni][1] * d0);
            if (r0 + 8 < n)
                *(__half2*)(g_hs + (size_t)(r0 + 8) * CC + col) =
                    __floats2half2_rn(c[mi][ni][2] * d1, c[mi][ni][3] * d1);
        }
    }
}

// ---------- k_agg: CSR gather + relu*x + LN + residual -> g_y (no FC) -------
// 256 threads = 8 warps, one warp per node. Nearly smem-free.
__global__ void k_agg(const float* __restrict__ x,
                      const float* __restrict__ bconv,
                      const float* __restrict__ gamma,
                      const float* __restrict__ beta,
                      int n) {
    __shared__ float bcs[CC], gs[CC], bs[CC];
    int t = threadIdx.x;
    if (t < CC) { bcs[t] = bconv[t]; gs[t] = gamma[t]; bs[t] = beta[t]; }
    __syncthreads();

    int wid = t >> 5;
    int lane = t & 31;
    int node = blockIdx.x * 8 + wid;
    if (node >= n) return;

    int rs = g_rowstart[node];
    int re = g_rowstart[node + 1];
    float dn = g_dinv[node];

    float4 acc;
    {
        uint2 raw = *((const uint2*)(g_hs + (size_t)node * CC) + lane);
        float2 f0 = __half22float2(*(__half2*)&raw.x);
        float2 f1 = __half22float2(*(__half2*)&raw.y);
        acc = make_float4(f0.x, f0.y, f1.x, f1.y);
    }

    for (int base = rs; base < re; base += 32) {
        int idx = base + lane;
        int s = (idx < re) ? g_esrc[idx] : 0;
        int m = min(32, re - base);
        int j = 0;
        for (; j + 8 <= m; j += 8) {
            int ss[8]; uint2 vv[8];
#pragma unroll
            for (int q = 0; q < 8; q++)
                ss[q] = __shfl_sync(0xffffffffu, s, j + q);
#pragma unroll
            for (int q = 0; q < 8; q++)
                vv[q] = *((const uint2*)(g_hs + (size_t)ss[q] * CC) + lane);
#pragma unroll
            for (int q = 0; q < 8; q++) {
                float2 f0 = __half22float2(*(__half2*)&vv[q].x);
                float2 f1 = __half22float2(*(__half2*)&vv[q].y);
                acc.x += f0.x; acc.y += f0.y; acc.z += f1.x; acc.w += f1.y;
            }
        }
        for (; j + 4 <= m; j += 4) {
            int ss[4]; uint2 vv[4];
#pragma unroll
            for (int q = 0; q < 4; q++)
                ss[q] = __shfl_sync(0xffffffffu, s, j + q);
#pragma unroll
            for (int q = 0; q < 4; q++)
                vv[q] = *((const uint2*)(g_hs + (size_t)ss[q] * CC) + lane);
#pragma unroll
            for (int q = 0; q < 4; q++) {
                float2 f0 = __half22float2(*(__half2*)&vv[q].x);
                float2 f1 = __half22float2(*(__half2*)&vv[q].y);
                acc.x += f0.x; acc.y += f0.y; acc.z += f1.x; acc.w += f1.y;
            }
        }
        for (; j < m; j++) {
            int sj = __shfl_sync(0xffffffffu, s, j);
            uint2 raw = *((const uint2*)(g_hs + (size_t)sj * CC) + lane);
            float2 f0 = __half22float2(*(__half2*)&raw.x);
            float2 f1 = __half22float2(*(__half2*)&raw.y);
            acc.x += f0.x; acc.y += f0.y; acc.z += f1.x; acc.w += f1.y;
        }
    }

    float4 xv = ((const float4*)(x + (size_t)node * CC))[lane];
    float4 bc = ((const float4*)bcs)[lane];
    acc.x = fmaxf(fmaf(acc.x, dn, bc.x), 0.f) * xv.x;
    acc.y = fmaxf(fmaf(acc.y, dn, bc.y), 0.f) * xv.y;
    acc.z = fmaxf(fmaf(acc.z, dn, bc.z), 0.f) * xv.z;
    acc.w = fmaxf(fmaf(acc.w, dn, bc.w), 0.f) * xv.w;

    float sU = acc.x + acc.y + acc.z + acc.w;
    float qU = acc.x * acc.x + acc.y * acc.y + acc.z * acc.z + acc.w * acc.w;
#pragma unroll
    for (int off = 16; off >= 1; off >>= 1) {
        sU += __shfl_xor_sync(0xffffffffu, sU, off);
        qU += __shfl_xor_sync(0xffffffffu, qU, off);
    }
    float mu = sU * (1.0f / CC);
    float var = qU * (1.0f / CC) - mu * mu;
    float rstd = rsqrtf(var + LN_EPS);

    float4 g = ((const float4*)gs)[lane];
    float4 b = ((const float4*)bs)[lane];
    float4 y;
    y.x = (acc.x - mu) * rstd * g.x + b.x + xv.x;
    y.y = (acc.y - mu) * rstd * g.y + b.y + xv.y;
    y.z = (acc.z - mu) * rstd * g.z + b.z + xv.z;
    y.w = (acc.w - mu) * rstd * g.w + b.w + xv.w;
    ((float4*)(g_y + (size_t)node * CC))[lane] = y;
}

// ---------------- k_fc: out = y @ W_fc + b_fc via mma.sync tf32 -------------
// 256 thr / 8 warps; tile 128 rows; warp w handles rows [w*16, w*16+16),
// all 40 cols (5 n-frags). K=128 in 16 steps.
#define YSTR 132
#define WSTR 44
#define FC_SMEM ((128 * YSTR + 128 * WSTR) * 4)

__global__ void __launch_bounds__(256, 1)
k_fc(const float* __restrict__ Wfc, const float* __restrict__ bfc,
     float* __restrict__ out, int n) {
    extern __shared__ float sm[];
    float* Ys = sm;                 // [128][YSTR]
    float* Ws = sm + 128 * YSTR;    // [128][WSTR]
    __shared__ float bfs[KK];
    int t = threadIdx.x;
    int w = t >> 5, lane = t & 31;
    int m0 = blockIdx.x * 128;

    for (int i = t; i < 128 * 32; i += 256) {
        int r = i >> 5, cs = i & 31;
        float4 v = make_float4(0.f, 0.f, 0.f, 0.f);
        if (m0 + r < n) v = ((const float4*)(g_y + (size_t)(m0 + r) * CC))[cs];
        float4 tv;
        tv.x = __uint_as_float(f2tf32(v.x));
        tv.y = __uint_as_float(f2tf32(v.y));
        tv.z = __uint_as_float(f2tf32(v.z));
        tv.w = __uint_as_float(f2tf32(v.w));
        *(float4*)(Ys + r * YSTR + cs * 4) = tv;
    }
    for (int i = t; i < 128 * 10; i += 256) {   // Wfc rows of 10 float4
        int r = i / 10, cs = i % 10;
        float4 v = ((const float4*)(Wfc + (size_t)r * KK))[cs];
        float4 tv;
        tv.x = __uint_as_float(f2tf32(v.x));
        tv.y = __uint_as_float(f2tf32(v.y));
        tv.z = __uint_as_float(f2tf32(v.z));
        tv.w = __uint_as_float(f2tf32(v.w));
        *(float4*)(Ws + r * WSTR + cs * 4) = tv;
    }
    if (t < KK) bfs[t] = bfc[t];
    __syncthreads();

    int grp = lane >> 2;
    int qd  = lane & 3;
    int r0 = w * 16 + grp;

    float c[5][4];
#pragma unroll
    for (int ni = 0; ni < 5; ni++)
#pragma unroll
        for (int q = 0; q < 4; q++) c[ni][q] = 0.f;

#pragma unroll
    for (int k0 = 0; k0 < 128; k0 += 8) {
        uint32_t a0 = __float_as_uint(Ys[r0 * YSTR + k0 + qd]);
        uint32_t a1 = __float_as_uint(Ys[(r0 + 8) * YSTR + k0 + qd]);
        uint32_t a2 = __float_as_uint(Ys[r0 * YSTR + k0 + qd + 4]);
        uint32_t a3 = __float_as_uint(Ys[(r0 + 8) * YSTR + k0 + qd + 4]);
#pragma unroll
        for (int ni = 0; ni < 5; ni++) {
            int nc = ni * 8 + grp;
            uint32_t b0 = __float_as_uint(Ws[(k0 + qd) * WSTR + nc]);
            uint32_t b1 = __float_as_uint(Ws[(k0 + qd + 4) * WSTR + nc]);
            asm volatile(
                "mma.sync.aligned.m16n8k8.row.col.f32.tf32.tf32.f32 "
                "{%0,%1,%2,%3}, {%4,%5,%6,%7}, {%8,%9}, {%0,%1,%2,%3};"
                : "+f"(c[ni][0]), "+f"(c[ni][1]), "+f"(c[ni][2]), "+f"(c[ni][3])
                : "r"(a0), "r"(a1), "r"(a2), "r"(a3), "r"(b0), "r"(b1));
        }
    }

    int row0 = m0 + w * 16 + grp;
#pragma unroll
    for (int ni = 0; ni < 5; ni++) {
        int col = ni * 8 + 2 * qd;
        float bq0 = bfs[col], bq1 = bfs[col + 1];
        if (row0 < n)
            *(float2*)(out + (size_t)row0 * KK + col) =
                make_float2(c[ni][0] + bq0, c[ni][1] + bq1);
        if (row0 + 8 < n)
            *(float2*)(out + (size_t)(row0 + 8) * KK + col) =
                make_float2(c[ni][2] + bq0, c[ni][3] + bq1);
    }
}

// ---------------------------------------------------------------- launch ----
extern "C" void kernel_launch(void* const* d_in, const int* in_sizes, int n_in,
                              void* d_out, int out_size) {
    const float* x  = (const float*)d_in[0];
    const int*   ei = (const int*)d_in[1];
    const float* Wc = (const float*)d_in[2];
    const float* bc = (const float*)d_in[3];
    const float* gm = (const float*)d_in[4];
    const float* bt = (const float*)d_in[5];
    const float* Wf = (const float*)d_in[6];
    const float* bf = (const float*)d_in[7];
    float* out = (float*)d_out;

    int n = in_sizes[0] / CC;
    int e = in_sizes[1] / 2;
    const int* src = ei;
    const int* dst = ei + e;
    int nb = (n + SCAN_BS - 1) / SCAN_BS;

    static void* cnt_ptr = nullptr;
    if (cnt_ptr == nullptr) {
        cudaGetSymbolAddress(&cnt_ptr, g_cnt);
        cudaFuncSetAttribute(k_gemm_mma, cudaFuncAttributeMaxDynamicSharedMemorySize,
                             GEMM_SMEM);
        cudaFuncSetAttribute(k_fc, cudaFuncAttributeMaxDynamicSharedMemorySize,
                             FC_SMEM);
    }

    cudaMemsetAsync(cnt_ptr, 0, (size_t)n * sizeof(int), 0);
    k_count<<<(e + 255) / 256, 256>>>(dst, e);
    k_scan1<<<nb, SCAN_BS>>>(n);
    k_scan23<<<nb, SCAN_BS>>>(n, e, nb);
    k_fill<<<(e + 255) / 256, 256>>>(src, dst, e);

    k_gemm_mma<<<(n + 127) / 128, 256, GEMM_SMEM>>>(x, Wc, n);

    k_agg<<<(n + 7) / 8, 256>>>(x, bc, gm, bt, n);
    k_fc<<<(n + 127) / 128, 256, FC_SMEM>>>(Wf, bf, out, n);
}